// round 2
// baseline (speedup 1.0000x reference)
#include <cuda_runtime.h>

// out[r,c] = x[r,c] * scale[c],  scale[c] = (u[c] >= 0.1f) ? vec[c] * (1/0.9f) : 0
// Shapes: x [131072, 1024] fp32, vec [1024], u [1024]. Pure HBM stream.

#define DEPTH 1024
#define P_DROP 0.1f

// Precomputed per-column scale (4 KB; L1/L2 resident during main kernel).
__device__ float g_scale[DEPTH];

__global__ void compute_scale_kernel(const float* __restrict__ vec,
                                     const float* __restrict__ u) {
    int c = blockIdx.x * blockDim.x + threadIdx.x;
    if (c < DEPTH) {
        float keep = (u[c] >= P_DROP) ? 1.0f : 0.0f;
        g_scale[c] = keep * vec[c] * (1.0f / (1.0f - P_DROP));
    }
}

__global__ void __launch_bounds__(256)
scale_cols_kernel(const float4* __restrict__ x,
                  float4* __restrict__ out,
                  int n4) {
    const float4* __restrict__ s4 = reinterpret_cast<const float4*>(g_scale);
    int stride = gridDim.x * blockDim.x;
    for (int i = blockIdx.x * blockDim.x + threadIdx.x; i < n4; i += stride) {
        // column (in float4 units) cycles with period DEPTH/4 = 256
        int c4 = i & (DEPTH / 4 - 1);
        float4 v = x[i];
        float4 s = s4[c4];           // L1 hit (4 KB working set)
        v.x *= s.x;
        v.y *= s.y;
        v.z *= s.z;
        v.w *= s.w;
        out[i] = v;
    }
}

extern "C" void kernel_launch(void* const* d_in, const int* in_sizes, int n_in,
                              void* d_out, int out_size) {
    const float* x   = (const float*)d_in[0];
    const float* vec = (const float*)d_in[1];
    const float* u   = (const float*)d_in[2];
    float* out = (float*)d_out;

    compute_scale_kernel<<<(DEPTH + 255) / 256, 256>>>(vec, u);

    int n4 = out_size / 4;  // 33,554,432 float4 elements
    // ~2 float4 per thread: enough blocks to cover the chip many times over,
    // grid-stride keeps it robust.
    int threads = 256;
    int blocks = 65536;  // 16.7M threads, 2 iterations each
    scale_cols_kernel<<<blocks, threads>>>((const float4*)x, (float4*)out, n4);
}